// round 12
// baseline (speedup 1.0000x reference)
#include <cuda_runtime.h>
#include <math.h>

#define N_NODES 16384
#define C_DIM   64
#define KNN     40
#define BUF     21
#define QPB     128       // queries per CTA (kNN)
#define W_HALF  2048      // half rank-window
#define TILE2   1024
#define SORT_T  1024
#define SBLK    32
#define BN_EPS  1e-5f
#define FBIG    1e30f

// ---------------- scratch (static device globals; no allocation) ----------------
__device__ float4 g_s4[N_NODES];               // coords by original id (w unused)
__device__ float4 g_ss[N_NODES];               // sorted coords (x,y,z,|p|^2)
__device__ int    g_sid[N_NODES];              // sorted pos -> original id
__device__ float  g_h[N_NODES * C_DIM];
__device__ int    g_idx[KNN * N_NODES];
__device__ float  g_ew[KNN * N_NODES];
__device__ float  g_t[N_NODES * C_DIM];
__device__ float  g_wres[N_NODES * C_DIM];
__device__ float  g_ps[2][SBLK][C_DIM], g_pq[2][SBLK][C_DIM];
__device__ float  g_mu2[C_DIM], g_rs2[C_DIM], g_mu3[C_DIM], g_rs3[C_DIM];

// ---------------- K1: h = x@w_h + b_h ; s = x@w_s ----------------
__global__ __launch_bounds__(512) void k_prep(const float* __restrict__ x,
                                              const float* __restrict__ w_h,
                                              const float* __restrict__ b_h,
                                              const float* __restrict__ w_s) {
    __shared__ float whs[C_DIM * C_DIM];
    __shared__ float wss[C_DIM * 4];
    __shared__ float sx[8][C_DIM];
    int tid = threadIdx.x;
    for (int i = tid; i < C_DIM * C_DIM; i += 512) whs[i] = w_h[i];
    if (tid < C_DIM * 3) wss[(tid / 3) * 4 + (tid % 3)] = w_s[tid];
    int g = tid >> 6, c = tid & 63;
    int n = blockIdx.x * 8 + g;
    sx[g][c] = x[n * C_DIM + c];
    __syncthreads();
    float acc = b_h[c];
#pragma unroll
    for (int k2 = 0; k2 < C_DIM; k2++) acc = fmaf(sx[g][k2], whs[k2 * C_DIM + c], acc);
    g_h[n * C_DIM + c] = acc;
    if (c < 4) {
        float sv = 0.f;
        if (c < 3) {
#pragma unroll
            for (int k2 = 0; k2 < C_DIM; k2++) sv = fmaf(sx[g][k2], wss[k2 * 4 + c], sv);
        }
        ((float*)g_s4)[n * 4 + c] = sv;
    }
}

// ---------------- K2: deterministic single-CTA bitonic sort by s.x ----------------
// Pure shared-memory pair processing: NO per-thread arrays anywhere, so nothing
// can spill to local memory (the round-5/9 killer: spilled u64 v[16] ->
// ~320 LDL/STL per thread per phase at the 4-cyc LSU floor on one SM ~= 2.2ms).
// Each (k,j) phase: 8192 pairs, 8 per thread, 2xLDS.64 + cswap + 2xSTS.64.
__global__ __launch_bounds__(SORT_T, 1) void k_sort() {
    extern __shared__ unsigned long long sk[];
    int tid = threadIdx.x;
    for (int i = tid; i < N_NODES; i += SORT_T) {
        unsigned int u = __float_as_uint(g_s4[i].x);
        u = (u & 0x80000000u) ? ~u : (u | 0x80000000u);   // sortable uint
        sk[i] = ((unsigned long long)u << 32) | (unsigned int)i;
    }
    __syncthreads();
    for (int k = 2; k <= N_NODES; k <<= 1) {
        for (int j = k >> 1; j >= 1; j >>= 1) {
#pragma unroll
            for (int s = 0; s < N_NODES / 2 / SORT_T; s++) {
                int p = tid + s * SORT_T;
                int i = ((p & ~(j - 1)) << 1) | (p & (j - 1));
                int l = i | j;
                unsigned long long A = sk[i], B = sk[l];
                bool up = ((i & k) == 0);
                if ((A > B) == up) { sk[i] = B; sk[l] = A; }
            }
            __syncthreads();
        }
    }
    for (int i = tid; i < N_NODES; i += SORT_T) {
        unsigned long long kv = sk[i];
        int id = (int)(kv & 0xFFFFFFFFull);
        float4 s = g_s4[id];
        float rp = fmaf(s.x, s.x, fmaf(s.y, s.y, s.z * s.z));
        g_ss[i] = make_float4(s.x, s.y, s.z, rp);
        g_sid[i] = id;
    }
}

// ---------------- K3: windowed exact kNN ----------------
__device__ __forceinline__ void insert40(float (&bd)[KNN], int (&bi)[KNN],
                                         float cd, int ci, bool want) {
    bool placed = !want;
#pragma unroll
    for (int j = KNN - 1; j >= 1; j--) {
        if (!placed) {
            bool sw = cd < bd[j - 1];
            float pu = bd[j - 1];
            int   iu = bi[j - 1];
            bd[j] = sw ? pu : cd;
            bi[j] = sw ? iu : ci;
            placed = !sw;
        }
        if ((j & 7) == 0) {
            if (__all_sync(0xffffffffu, placed)) return;
        }
    }
    if (!placed) { bd[0] = cd; bi[0] = ci; }
}

__device__ __forceinline__ void insert40_ser(float (&bd)[KNN], int (&bi)[KNN],
                                             float cd, int ci) {
    bool placed = false;
#pragma unroll
    for (int j = KNN - 1; j >= 1; j--) {
        if (!placed) {
            bool sw = cd < bd[j - 1];
            float pu = bd[j - 1];
            int   iu = bi[j - 1];
            bd[j] = sw ? pu : cd;
            bi[j] = sw ? iu : ci;
            placed = !sw;
        }
    }
    if (!placed) { bd[0] = cd; bi[0] = ci; }
}

__device__ __forceinline__ void flush_buf(float (&bd)[KNN], int (&bi)[KNN],
                                          float (*bufD)[BUF], int (*bufI)[BUF],
                                          int tid, int& cnt) {
    int mx = cnt;
#pragma unroll
    for (int o = 16; o > 0; o >>= 1)
        mx = max(mx, __shfl_xor_sync(0xffffffffu, mx, o));
    for (int e = 0; e < mx; e++) {
        bool act = e < cnt;
        float d = act ? bufD[tid][e] : FBIG;
        int idv = act ? bufI[tid][e] : 0;
        insert40(bd, bi, d, idv, act && (d < bd[KNN - 1]));
    }
    cnt = 0;
}

__global__ __launch_bounds__(QPB) void k_knn() {
    __shared__ float4 shp[TILE2];          // 16KB
    __shared__ float  bufD[QPB][BUF];      // 10.5KB
    __shared__ int    bufI[QPB][BUF];      // 10.5KB
    int tid = threadIdx.x;
    int p = blockIdx.x * QPB + tid;        // my query's sorted position
    float4 qs = g_ss[p];
    float qx2 = -2.f * qs.x, qy2 = -2.f * qs.y, qz2 = -2.f * qs.z;
    float sq = qs.w;
    float bd[KNN]; int bi[KNN];
#pragma unroll
    for (int j = 0; j < KNN; j++) { bd[j] = FBIG; bi[j] = 0; }
    int lo = blockIdx.x * QPB - W_HALF; if (lo < 0) lo = 0;
    int hi = blockIdx.x * QPB + QPB + W_HALF; if (hi > N_NODES) hi = N_NODES;
    int cnt = 0;

    for (int t0 = lo; t0 < hi; t0 += TILE2) {
        int len = min(TILE2, hi - t0);
        for (int i2 = tid; i2 < len; i2 += QPB) shp[i2] = g_ss[t0 + i2];
        __syncthreads();
        int len8 = len & ~7;
        for (int j = 0; j < len8; j += 8) {
#pragma unroll
            for (int u = 0; u < 8; u++) {
                float4 c = shp[j + u];
                float t = fmaf(qx2, c.x, fmaf(qy2, c.y, fmaf(qz2, c.z, c.w)));
                if (t < bd[KNN - 1]) {
                    bufD[tid][cnt] = t;
                    bufI[tid][cnt] = t0 + j + u;
                    cnt++;
                }
            }
            if (__any_sync(0xffffffffu, cnt >= BUF - 8))
                flush_buf(bd, bi, bufD, bufI, tid, cnt);
        }
        for (int j = len8; j < len; j++) {
            float4 c = shp[j];
            float t = fmaf(qx2, c.x, fmaf(qy2, c.y, fmaf(qz2, c.z, c.w)));
            if (t < bd[KNN - 1]) {
                bufD[tid][cnt] = t;
                bufI[tid][cnt] = t0 + j;
                cnt++;
            }
        }
        if (__any_sync(0xffffffffu, cnt >= BUF - 8))
            flush_buf(bd, bi, bufD, bufI, tid, cnt);
        __syncthreads();
    }
    flush_buf(bd, bi, bufD, bufI, tid, cnt);

    // ---- Phase B: provably-exact extension past the window ----
    float thrd = sq + bd[KNN - 1];          // absolute d2 of current 40th
    {   // left: px <= qx, |dx| increases as i decreases
        int i = lo - 1;
        bool go = (i >= 0);
        while (go) {
            int m = min(4, i + 1);
            float4 c[4];
#pragma unroll
            for (int u = 0; u < 4; u++) if (u < m) c[u] = g_ss[i - u];
#pragma unroll
            for (int u = 0; u < 4; u++) {
                if (go && u < m) {
                    float dx = qs.x - c[u].x;
                    if (dx * dx >= thrd) { go = false; }
                    else {
                        float t = fmaf(qx2, c[u].x, fmaf(qy2, c[u].y, fmaf(qz2, c[u].z, c[u].w)));
                        if (t < bd[KNN - 1]) {
                            insert40_ser(bd, bi, t, i - u);
                            thrd = sq + bd[KNN - 1];
                        }
                    }
                }
            }
            i -= m;
            if (i < 0) go = false;
        }
    }
    {   // right: px >= qx
        int i = hi;
        bool go = (i < N_NODES);
        while (go) {
            int m = min(4, N_NODES - i);
            float4 c[4];
#pragma unroll
            for (int u = 0; u < 4; u++) if (u < m) c[u] = g_ss[i + u];
#pragma unroll
            for (int u = 0; u < 4; u++) {
                if (go && u < m) {
                    float dx = qs.x - c[u].x;
                    if (dx * dx >= thrd) { go = false; }
                    else {
                        float t = fmaf(qx2, c[u].x, fmaf(qy2, c[u].y, fmaf(qz2, c[u].z, c[u].w)));
                        if (t < bd[KNN - 1]) {
                            insert40_ser(bd, bi, t, i + u);
                            thrd = sq + bd[KNN - 1];
                        }
                    }
                }
            }
            i += m;
            if (i >= N_NODES) go = false;
        }
    }

    int qid = g_sid[p];
#pragma unroll
    for (int j = 0; j < KNN; j++) {
        g_idx[j * N_NODES + qid] = g_sid[bi[j]];
        g_ew[j * N_NODES + qid] = expf(-(sq + bd[j] + 1e-6f));
    }
}

// ---------------- K4: gather-aggregate (mean,max) + lin(cat) + residual ----------------
__global__ __launch_bounds__(512) void k_agglin(const float* __restrict__ x,
                                                const float* __restrict__ w_lin,
                                                const float* __restrict__ b_lin) {
    __shared__ float Ws[128 * 64];
    __shared__ float scat[8][128];
    __shared__ float sx[8][64];
    int tid = threadIdx.x;
    for (int i = tid; i < (128 * 64) / 4; i += 512)
        ((float4*)Ws)[i] = ((const float4*)w_lin)[i];
    int g = tid >> 6, c = tid & 63;
    int n = blockIdx.x * 8 + g;
    float mean = 0.f, mx = -FBIG;
#pragma unroll 1
    for (int k2 = 0; k2 < KNN; k2 += 8) {
        int ii[8]; float ww[8];
#pragma unroll
        for (int u = 0; u < 8; u++) {
            ii[u] = g_idx[(k2 + u) * N_NODES + n];
            ww[u] = g_ew[(k2 + u) * N_NODES + n];
        }
#pragma unroll
        for (int u = 0; u < 8; u++) {
            float m = ww[u] * g_h[ii[u] * C_DIM + c];
            mean += m;
            mx = fmaxf(mx, m);
        }
    }
    mean *= (1.0f / KNN);
    float xv = x[n * C_DIM + c];
    scat[g][c] = mean;
    scat[g][64 + c] = mx;
    sx[g][c] = xv;
    __syncthreads();
    float acc = b_lin[c];
#pragma unroll
    for (int j = 0; j < 128; j++) acc = fmaf(scat[g][j], Ws[j * 64 + c], acc);
#pragma unroll
    for (int j = 0; j < 64; j++)
        acc = fmaf(sx[g][j], __ldg(&w_lin[(128 + j) * 64 + c]), acc);
    g_t[n * C_DIM + c] = acc + xv;
}

// ---------------- coalesced deterministic BN stats ----------------
__global__ __launch_bounds__(256) void k_stats_part(int which) {
    const float* v = (which == 0) ? g_t : g_wres;
    __shared__ float4 rs_[256], rq_[256];
    int tid = threadIdx.x;
    int cg = tid & 15, ns = tid >> 4;
    float4 s = {0.f, 0.f, 0.f, 0.f}, sq = {0.f, 0.f, 0.f, 0.f};
    int nbase = blockIdx.x * (N_NODES / SBLK);
#pragma unroll 4
    for (int n = nbase + ns; n < nbase + (N_NODES / SBLK); n += 16) {
        float4 val = ((const float4*)v)[n * 16 + cg];
        s.x += val.x; s.y += val.y; s.z += val.z; s.w += val.w;
        sq.x = fmaf(val.x, val.x, sq.x); sq.y = fmaf(val.y, val.y, sq.y);
        sq.z = fmaf(val.z, val.z, sq.z); sq.w = fmaf(val.w, val.w, sq.w);
    }
    rs_[tid] = s; rq_[tid] = sq;
    __syncthreads();
    for (int off = 128; off >= 16; off >>= 1) {
        if (tid < off) {
            float4 a = rs_[tid], b = rs_[tid + off];
            a.x += b.x; a.y += b.y; a.z += b.z; a.w += b.w;
            rs_[tid] = a;
            float4 c = rq_[tid], d = rq_[tid + off];
            c.x += d.x; c.y += d.y; c.z += d.z; c.w += d.w;
            rq_[tid] = c;
        }
        __syncthreads();
    }
    if (tid < 16) {
        float4 a = rs_[tid], b = rq_[tid];
        g_ps[which][blockIdx.x][tid * 4 + 0] = a.x;
        g_ps[which][blockIdx.x][tid * 4 + 1] = a.y;
        g_ps[which][blockIdx.x][tid * 4 + 2] = a.z;
        g_ps[which][blockIdx.x][tid * 4 + 3] = a.w;
        g_pq[which][blockIdx.x][tid * 4 + 0] = b.x;
        g_pq[which][blockIdx.x][tid * 4 + 1] = b.y;
        g_pq[which][blockIdx.x][tid * 4 + 2] = b.z;
        g_pq[which][blockIdx.x][tid * 4 + 3] = b.w;
    }
}

__global__ void k_stats_fin(int which) {
    int c = threadIdx.x;
    float s = 0.f, s2 = 0.f;
#pragma unroll
    for (int b = 0; b < SBLK; b++) {
        s += g_ps[which][b][c];
        s2 += g_pq[which][b][c];
    }
    float m = s * (1.0f / N_NODES);
    float var = s2 * (1.0f / N_NODES) - m * m;
    if (which == 0) { g_mu2[c] = m; g_rs2[c] = rsqrtf(var + BN_EPS); }
    else            { g_mu3[c] = m; g_rs3[c] = rsqrtf(var + BN_EPS); }
}

// ---------------- K5: BN2 + MLP + residual ----------------
__global__ __launch_bounds__(512) void k_mlp(const float* __restrict__ w_p1,
                                             const float* __restrict__ b_p1,
                                             const float* __restrict__ w_p2,
                                             const float* __restrict__ b_p2,
                                             const float* __restrict__ gamma2,
                                             const float* __restrict__ beta2) {
    __shared__ float w1s[64 * 64], w2s[64 * 64];
    __shared__ float sy[8][64], sa[8][64];
    int tid = threadIdx.x;
    for (int i = tid; i < (64 * 64) / 4; i += 512) {
        ((float4*)w1s)[i] = ((const float4*)w_p1)[i];
        ((float4*)w2s)[i] = ((const float4*)w_p2)[i];
    }
    int g = tid >> 6, c = tid & 63;
    int n = blockIdx.x * 8 + g;
    float y = gamma2[c] * (g_t[n * 64 + c] - g_mu2[c]) * g_rs2[c] + beta2[c];
    sy[g][c] = y;
    __syncthreads();
    float a = b_p1[c];
#pragma unroll
    for (int k2 = 0; k2 < 64; k2++) a = fmaf(sy[g][k2], w1s[k2 * 64 + c], a);
    a = (a > 0.f) ? a : expm1f(a);
    sa[g][c] = a;
    __syncthreads();
    float z = b_p2[c];
#pragma unroll
    for (int k2 = 0; k2 < 64; k2++) z = fmaf(sa[g][k2], w2s[k2 * 64 + c], z);
    g_wres[n * 64 + c] = y + z;
}

// ---------------- K6: out = BN3(wres) ----------------
__global__ void k_bn3(float* __restrict__ out,
                      const float* __restrict__ gamma3,
                      const float* __restrict__ beta3) {
    int i = blockIdx.x * 256 + threadIdx.x;
    float4 wv = ((const float4*)g_wres)[i];
    int cb = (i & 15) * 4;
    float4 o;
    o.x = gamma3[cb + 0] * (wv.x - g_mu3[cb + 0]) * g_rs3[cb + 0] + beta3[cb + 0];
    o.y = gamma3[cb + 1] * (wv.y - g_mu3[cb + 1]) * g_rs3[cb + 1] + beta3[cb + 1];
    o.z = gamma3[cb + 2] * (wv.z - g_mu3[cb + 2]) * g_rs3[cb + 2] + beta3[cb + 2];
    o.w = gamma3[cb + 3] * (wv.w - g_mu3[cb + 3]) * g_rs3[cb + 3] + beta3[cb + 3];
    ((float4*)out)[i] = o;
}

// ---------------- launch ----------------
extern "C" void kernel_launch(void* const* d_in, const int* in_sizes, int n_in,
                              void* d_out, int out_size) {
    const float* x      = (const float*)d_in[0];
    const float* w_s    = (const float*)d_in[1];
    const float* w_h    = (const float*)d_in[2];
    const float* b_h    = (const float*)d_in[3];
    const float* w_lin  = (const float*)d_in[4];
    const float* b_lin  = (const float*)d_in[5];
    const float* w_p1   = (const float*)d_in[6];
    const float* b_p1   = (const float*)d_in[7];
    const float* w_p2   = (const float*)d_in[8];
    const float* b_p2   = (const float*)d_in[9];
    const float* gamma2 = (const float*)d_in[10];
    const float* beta2  = (const float*)d_in[11];
    const float* gamma3 = (const float*)d_in[12];
    const float* beta3  = (const float*)d_in[13];
    float* out = (float*)d_out;

    static int smem_set = 0;
    if (!smem_set) {
        cudaFuncSetAttribute(k_sort, cudaFuncAttributeMaxDynamicSharedMemorySize,
                             N_NODES * (int)sizeof(unsigned long long));
        smem_set = 1;
    }

    k_prep<<<N_NODES / 8, 512>>>(x, w_h, b_h, w_s);
    k_sort<<<1, SORT_T, N_NODES * sizeof(unsigned long long)>>>();
    k_knn<<<N_NODES / QPB, QPB>>>();
    k_agglin<<<N_NODES / 8, 512>>>(x, w_lin, b_lin);
    k_stats_part<<<SBLK, 256>>>(0);
    k_stats_fin<<<1, C_DIM>>>(0);
    k_mlp<<<N_NODES / 8, 512>>>(w_p1, b_p1, w_p2, b_p2, gamma2, beta2);
    k_stats_part<<<SBLK, 256>>>(1);
    k_stats_fin<<<1, C_DIM>>>(1);
    k_bn3<<<(N_NODES * C_DIM) / 4 / 256, 256>>>(out, gamma3, beta3);
}

// round 13
// speedup vs baseline: 1.0024x; 1.0024x over previous
#include <cuda_runtime.h>
#include <math.h>

#define N_NODES 16384
#define C_DIM   64
#define KNN     40
#define BUF     21
#define QPB     128       // queries per CTA (kNN)
#define W_HALF  2048      // half rank-window
#define WINCAP  4352      // padded window capacity (>= 2*W_HALF + QPB)
#define SORT_T  1024
#define SBLK    32
#define BN_EPS  1e-5f
#define FBIG    1e30f

// ---------------- scratch (static device globals; no allocation) ----------------
__device__ float4 g_s4[N_NODES];               // coords by original id (w unused)
__device__ float4 g_ss[N_NODES];               // sorted coords (x,y,z,|p|^2)
__device__ int    g_sid[N_NODES];              // sorted pos -> original id
__device__ float  g_h[N_NODES * C_DIM];
__device__ int    g_idx[KNN * N_NODES];
__device__ float  g_ew[KNN * N_NODES];
__device__ float  g_t[N_NODES * C_DIM];
__device__ float  g_wres[N_NODES * C_DIM];
__device__ float  g_ps[2][SBLK][C_DIM], g_pq[2][SBLK][C_DIM];
__device__ float  g_mu2[C_DIM], g_rs2[C_DIM], g_mu3[C_DIM], g_rs3[C_DIM];

// ---------------- K1: h = x@w_h + b_h ; s = x@w_s ----------------
__global__ __launch_bounds__(512) void k_prep(const float* __restrict__ x,
                                              const float* __restrict__ w_h,
                                              const float* __restrict__ b_h,
                                              const float* __restrict__ w_s) {
    __shared__ float whs[C_DIM * C_DIM];
    __shared__ float wss[C_DIM * 4];
    __shared__ float sx[8][C_DIM];
    int tid = threadIdx.x;
    for (int i = tid; i < C_DIM * C_DIM; i += 512) whs[i] = w_h[i];
    if (tid < C_DIM * 3) wss[(tid / 3) * 4 + (tid % 3)] = w_s[tid];
    int g = tid >> 6, c = tid & 63;
    int n = blockIdx.x * 8 + g;
    sx[g][c] = x[n * C_DIM + c];
    __syncthreads();
    float acc = b_h[c];
#pragma unroll
    for (int k2 = 0; k2 < C_DIM; k2++) acc = fmaf(sx[g][k2], whs[k2 * C_DIM + c], acc);
    g_h[n * C_DIM + c] = acc;
    if (c < 4) {
        float sv = 0.f;
        if (c < 3) {
#pragma unroll
            for (int k2 = 0; k2 < C_DIM; k2++) sv = fmaf(sx[g][k2], wss[k2 * 4 + c], sv);
        }
        ((float*)g_s4)[n * 4 + c] = sv;
    }
}

// ---------------- K2: deterministic single-CTA bitonic sort by s.x ----------------
__global__ __launch_bounds__(SORT_T, 1) void k_sort() {
    extern __shared__ unsigned long long sk[];
    int tid = threadIdx.x;
    for (int i = tid; i < N_NODES; i += SORT_T) {
        unsigned int u = __float_as_uint(g_s4[i].x);
        u = (u & 0x80000000u) ? ~u : (u | 0x80000000u);   // sortable uint
        sk[i] = ((unsigned long long)u << 32) | (unsigned int)i;
    }
    __syncthreads();
    for (int k = 2; k <= N_NODES; k <<= 1) {
        for (int j = k >> 1; j >= 1; j >>= 1) {
#pragma unroll
            for (int s = 0; s < N_NODES / 2 / SORT_T; s++) {
                int p = tid + s * SORT_T;
                int i = ((p & ~(j - 1)) << 1) | (p & (j - 1));
                int l = i | j;
                unsigned long long A = sk[i], B = sk[l];
                bool up = ((i & k) == 0);
                if ((A > B) == up) { sk[i] = B; sk[l] = A; }
            }
            __syncthreads();
        }
    }
    for (int i = tid; i < N_NODES; i += SORT_T) {
        unsigned long long kv = sk[i];
        int id = (int)(kv & 0xFFFFFFFFull);
        float4 s = g_s4[id];
        float rp = fmaf(s.x, s.x, fmaf(s.y, s.y, s.z * s.z));
        g_ss[i] = make_float4(s.x, s.y, s.z, rp);
        g_sid[i] = id;
    }
}

// ---------------- K3: windowed exact kNN (bit-reversed eval order) ----------------
__device__ __forceinline__ void insert40(float (&bd)[KNN], int (&bi)[KNN],
                                         float cd, int ci, bool want) {
    bool placed = !want;
#pragma unroll
    for (int j = KNN - 1; j >= 1; j--) {
        if (!placed) {
            bool sw = cd < bd[j - 1];
            float pu = bd[j - 1];
            int   iu = bi[j - 1];
            bd[j] = sw ? pu : cd;
            bi[j] = sw ? iu : ci;
            placed = !sw;
        }
        if ((j & 7) == 0) {
            if (__all_sync(0xffffffffu, placed)) return;
        }
    }
    if (!placed) { bd[0] = cd; bi[0] = ci; }
}

__device__ __forceinline__ void insert40_ser(float (&bd)[KNN], int (&bi)[KNN],
                                             float cd, int ci) {
    bool placed = false;
#pragma unroll
    for (int j = KNN - 1; j >= 1; j--) {
        if (!placed) {
            bool sw = cd < bd[j - 1];
            float pu = bd[j - 1];
            int   iu = bi[j - 1];
            bd[j] = sw ? pu : cd;
            bi[j] = sw ? iu : ci;
            placed = !sw;
        }
    }
    if (!placed) { bd[0] = cd; bi[0] = ci; }
}

__device__ __forceinline__ void flush_buf(float (&bd)[KNN], int (&bi)[KNN],
                                          float (*bufD)[BUF], int (*bufI)[BUF],
                                          int tid, int& cnt) {
    int mx = cnt;
#pragma unroll
    for (int o = 16; o > 0; o >>= 1)
        mx = max(mx, __shfl_xor_sync(0xffffffffu, mx, o));
    for (int e = 0; e < mx; e++) {
        bool act = e < cnt;
        float d = act ? bufD[tid][e] : FBIG;
        int idv = act ? bufI[tid][e] : 0;
        insert40(bd, bi, d, idv, act && (d < bd[KNN - 1]));
    }
    cnt = 0;
}

__global__ __launch_bounds__(QPB) void k_knn() {
    extern __shared__ float4 win[];        // WINCAP * 16B = 68KB dynamic
    __shared__ float  bufD[QPB][BUF];      // 10.5KB
    __shared__ int    bufI[QPB][BUF];      // 10.5KB
    int tid = threadIdx.x;
    int p = blockIdx.x * QPB + tid;        // my query's sorted position
    float4 qs = g_ss[p];
    float qx2 = -2.f * qs.x, qy2 = -2.f * qs.y, qz2 = -2.f * qs.z;
    float sq = qs.w;
    float bd[KNN]; int bi[KNN];
#pragma unroll
    for (int j = 0; j < KNN; j++) { bd[j] = FBIG; bi[j] = 0; }
    int lo = blockIdx.x * QPB - W_HALF; if (lo < 0) lo = 0;
    int hi = blockIdx.x * QPB + QPB + W_HALF; if (hi > N_NODES) hi = N_NODES;
    int len = hi - lo;
    int cnt = 0;

    // load entire window; pad with +inf rows (t evaluates to +inf -> never inserts)
    const float INF = __int_as_float(0x7f800000);
    for (int i = tid; i < WINCAP; i += QPB)
        win[i] = (i < len) ? g_ss[lo + i] : make_float4(0.f, 0.f, 0.f, INF);
    __syncthreads();

    // main sweep: 12-bit bit-reversed order over [0,4096) decorrelates distance
    // from scan position (sorted order made ~every candidate an insert: the
    // rounds-5..12 2.2ms pathology). Warp-uniform idx -> smem broadcast.
    for (int j = 0; j < 4096; j += 8) {
#pragma unroll
        for (int u = 0; u < 8; u++) {
            int idx = (int)(__brev((unsigned)(j + u)) >> 20);
            float4 c = win[idx];
            float t = fmaf(qx2, c.x, fmaf(qy2, c.y, fmaf(qz2, c.z, c.w)));
            if (t < bd[KNN - 1]) {
                bufD[tid][cnt] = t;
                bufI[tid][cnt] = lo + idx;
                cnt++;
            }
        }
        if (__any_sync(0xffffffffu, cnt >= BUF - 8))
            flush_buf(bd, bi, bufD, bufI, tid, cnt);
    }
    // tail [4096, WINCAP): linear (at most 128 real entries)
    for (int j = 4096; j < WINCAP; j += 8) {
#pragma unroll
        for (int u = 0; u < 8; u++) {
            float4 c = win[j + u];
            float t = fmaf(qx2, c.x, fmaf(qy2, c.y, fmaf(qz2, c.z, c.w)));
            if (t < bd[KNN - 1]) {
                bufD[tid][cnt] = t;
                bufI[tid][cnt] = lo + j + u;
                cnt++;
            }
        }
        if (__any_sync(0xffffffffu, cnt >= BUF - 8))
            flush_buf(bd, bi, bufD, bufI, tid, cnt);
    }
    flush_buf(bd, bi, bufD, bufI, tid, cnt);

    // ---- Phase B: provably-exact extension past the window ----
    float thrd = sq + bd[KNN - 1];          // absolute d2 of current 40th
    {   // left: px <= qx, |dx| increases as i decreases
        int i = lo - 1;
        bool go = (i >= 0);
        while (go) {
            int m = min(4, i + 1);
            float4 c[4];
#pragma unroll
            for (int u = 0; u < 4; u++) if (u < m) c[u] = g_ss[i - u];
#pragma unroll
            for (int u = 0; u < 4; u++) {
                if (go && u < m) {
                    float dx = qs.x - c[u].x;
                    if (dx * dx >= thrd) { go = false; }
                    else {
                        float t = fmaf(qx2, c[u].x, fmaf(qy2, c[u].y, fmaf(qz2, c[u].z, c[u].w)));
                        if (t < bd[KNN - 1]) {
                            insert40_ser(bd, bi, t, i - u);
                            thrd = sq + bd[KNN - 1];
                        }
                    }
                }
            }
            i -= m;
            if (i < 0) go = false;
        }
    }
    {   // right: px >= qx
        int i = hi;
        bool go = (i < N_NODES);
        while (go) {
            int m = min(4, N_NODES - i);
            float4 c[4];
#pragma unroll
            for (int u = 0; u < 4; u++) if (u < m) c[u] = g_ss[i + u];
#pragma unroll
            for (int u = 0; u < 4; u++) {
                if (go && u < m) {
                    float dx = qs.x - c[u].x;
                    if (dx * dx >= thrd) { go = false; }
                    else {
                        float t = fmaf(qx2, c[u].x, fmaf(qy2, c[u].y, fmaf(qz2, c[u].z, c[u].w)));
                        if (t < bd[KNN - 1]) {
                            insert40_ser(bd, bi, t, i + u);
                            thrd = sq + bd[KNN - 1];
                        }
                    }
                }
            }
            i += m;
            if (i >= N_NODES) go = false;
        }
    }

    int qid = g_sid[p];
#pragma unroll
    for (int j = 0; j < KNN; j++) {
        g_idx[j * N_NODES + qid] = g_sid[bi[j]];
        g_ew[j * N_NODES + qid] = expf(-(sq + bd[j] + 1e-6f));
    }
}

// ---------------- K4: gather-aggregate (mean,max) + lin(cat) + residual ----------------
__global__ __launch_bounds__(512) void k_agglin(const float* __restrict__ x,
                                                const float* __restrict__ w_lin,
                                                const float* __restrict__ b_lin) {
    __shared__ float Ws[128 * 64];
    __shared__ float scat[8][128];
    __shared__ float sx[8][64];
    int tid = threadIdx.x;
    for (int i = tid; i < (128 * 64) / 4; i += 512)
        ((float4*)Ws)[i] = ((const float4*)w_lin)[i];
    int g = tid >> 6, c = tid & 63;
    int n = blockIdx.x * 8 + g;
    float mean = 0.f, mx = -FBIG;
#pragma unroll 1
    for (int k2 = 0; k2 < KNN; k2 += 8) {
        int ii[8]; float ww[8];
#pragma unroll
        for (int u = 0; u < 8; u++) {
            ii[u] = g_idx[(k2 + u) * N_NODES + n];
            ww[u] = g_ew[(k2 + u) * N_NODES + n];
        }
#pragma unroll
        for (int u = 0; u < 8; u++) {
            float m = ww[u] * g_h[ii[u] * C_DIM + c];
            mean += m;
            mx = fmaxf(mx, m);
        }
    }
    mean *= (1.0f / KNN);
    float xv = x[n * C_DIM + c];
    scat[g][c] = mean;
    scat[g][64 + c] = mx;
    sx[g][c] = xv;
    __syncthreads();
    float acc = b_lin[c];
#pragma unroll
    for (int j = 0; j < 128; j++) acc = fmaf(scat[g][j], Ws[j * 64 + c], acc);
#pragma unroll
    for (int j = 0; j < 64; j++)
        acc = fmaf(sx[g][j], __ldg(&w_lin[(128 + j) * 64 + c]), acc);
    g_t[n * C_DIM + c] = acc + xv;
}

// ---------------- coalesced deterministic BN stats ----------------
__global__ __launch_bounds__(256) void k_stats_part(int which) {
    const float* v = (which == 0) ? g_t : g_wres;
    __shared__ float4 rs_[256], rq_[256];
    int tid = threadIdx.x;
    int cg = tid & 15, ns = tid >> 4;
    float4 s = {0.f, 0.f, 0.f, 0.f}, sq = {0.f, 0.f, 0.f, 0.f};
    int nbase = blockIdx.x * (N_NODES / SBLK);
#pragma unroll 4
    for (int n = nbase + ns; n < nbase + (N_NODES / SBLK); n += 16) {
        float4 val = ((const float4*)v)[n * 16 + cg];
        s.x += val.x; s.y += val.y; s.z += val.z; s.w += val.w;
        sq.x = fmaf(val.x, val.x, sq.x); sq.y = fmaf(val.y, val.y, sq.y);
        sq.z = fmaf(val.z, val.z, sq.z); sq.w = fmaf(val.w, val.w, sq.w);
    }
    rs_[tid] = s; rq_[tid] = sq;
    __syncthreads();
    for (int off = 128; off >= 16; off >>= 1) {
        if (tid < off) {
            float4 a = rs_[tid], b = rs_[tid + off];
            a.x += b.x; a.y += b.y; a.z += b.z; a.w += b.w;
            rs_[tid] = a;
            float4 c = rq_[tid], d = rq_[tid + off];
            c.x += d.x; c.y += d.y; c.z += d.z; c.w += d.w;
            rq_[tid] = c;
        }
        __syncthreads();
    }
    if (tid < 16) {
        float4 a = rs_[tid], b = rq_[tid];
        g_ps[which][blockIdx.x][tid * 4 + 0] = a.x;
        g_ps[which][blockIdx.x][tid * 4 + 1] = a.y;
        g_ps[which][blockIdx.x][tid * 4 + 2] = a.z;
        g_ps[which][blockIdx.x][tid * 4 + 3] = a.w;
        g_pq[which][blockIdx.x][tid * 4 + 0] = b.x;
        g_pq[which][blockIdx.x][tid * 4 + 1] = b.y;
        g_pq[which][blockIdx.x][tid * 4 + 2] = b.z;
        g_pq[which][blockIdx.x][tid * 4 + 3] = b.w;
    }
}

__global__ void k_stats_fin(int which) {
    int c = threadIdx.x;
    float s = 0.f, s2 = 0.f;
#pragma unroll
    for (int b = 0; b < SBLK; b++) {
        s += g_ps[which][b][c];
        s2 += g_pq[which][b][c];
    }
    float m = s * (1.0f / N_NODES);
    float var = s2 * (1.0f / N_NODES) - m * m;
    if (which == 0) { g_mu2[c] = m; g_rs2[c] = rsqrtf(var + BN_EPS); }
    else            { g_mu3[c] = m; g_rs3[c] = rsqrtf(var + BN_EPS); }
}

// ---------------- K5: BN2 + MLP + residual ----------------
__global__ __launch_bounds__(512) void k_mlp(const float* __restrict__ w_p1,
                                             const float* __restrict__ b_p1,
                                             const float* __restrict__ w_p2,
                                             const float* __restrict__ b_p2,
                                             const float* __restrict__ gamma2,
                                             const float* __restrict__ beta2) {
    __shared__ float w1s[64 * 64], w2s[64 * 64];
    __shared__ float sy[8][64], sa[8][64];
    int tid = threadIdx.x;
    for (int i = tid; i < (64 * 64) / 4; i += 512) {
        ((float4*)w1s)[i] = ((const float4*)w_p1)[i];
        ((float4*)w2s)[i] = ((const float4*)w_p2)[i];
    }
    int g = tid >> 6, c = tid & 63;
    int n = blockIdx.x * 8 + g;
    float y = gamma2[c] * (g_t[n * 64 + c] - g_mu2[c]) * g_rs2[c] + beta2[c];
    sy[g][c] = y;
    __syncthreads();
    float a = b_p1[c];
#pragma unroll
    for (int k2 = 0; k2 < 64; k2++) a = fmaf(sy[g][k2], w1s[k2 * 64 + c], a);
    a = (a > 0.f) ? a : expm1f(a);
    sa[g][c] = a;
    __syncthreads();
    float z = b_p2[c];
#pragma unroll
    for (int k2 = 0; k2 < 64; k2++) z = fmaf(sa[g][k2], w2s[k2 * 64 + c], z);
    g_wres[n * 64 + c] = y + z;
}

// ---------------- K6: out = BN3(wres) ----------------
__global__ void k_bn3(float* __restrict__ out,
                      const float* __restrict__ gamma3,
                      const float* __restrict__ beta3) {
    int i = blockIdx.x * 256 + threadIdx.x;
    float4 wv = ((const float4*)g_wres)[i];
    int cb = (i & 15) * 4;
    float4 o;
    o.x = gamma3[cb + 0] * (wv.x - g_mu3[cb + 0]) * g_rs3[cb + 0] + beta3[cb + 0];
    o.y = gamma3[cb + 1] * (wv.y - g_mu3[cb + 1]) * g_rs3[cb + 1] + beta3[cb + 1];
    o.z = gamma3[cb + 2] * (wv.z - g_mu3[cb + 2]) * g_rs3[cb + 2] + beta3[cb + 2];
    o.w = gamma3[cb + 3] * (wv.w - g_mu3[cb + 3]) * g_rs3[cb + 3] + beta3[cb + 3];
    ((float4*)out)[i] = o;
}

// ---------------- launch ----------------
extern "C" void kernel_launch(void* const* d_in, const int* in_sizes, int n_in,
                              void* d_out, int out_size) {
    const float* x      = (const float*)d_in[0];
    const float* w_s    = (const float*)d_in[1];
    const float* w_h    = (const float*)d_in[2];
    const float* b_h    = (const float*)d_in[3];
    const float* w_lin  = (const float*)d_in[4];
    const float* b_lin  = (const float*)d_in[5];
    const float* w_p1   = (const float*)d_in[6];
    const float* b_p1   = (const float*)d_in[7];
    const float* w_p2   = (const float*)d_in[8];
    const float* b_p2   = (const float*)d_in[9];
    const float* gamma2 = (const float*)d_in[10];
    const float* beta2  = (const float*)d_in[11];
    const float* gamma3 = (const float*)d_in[12];
    const float* beta3  = (const float*)d_in[13];
    float* out = (float*)d_out;

    static int smem_set = 0;
    if (!smem_set) {
        cudaFuncSetAttribute(k_sort, cudaFuncAttributeMaxDynamicSharedMemorySize,
                             N_NODES * (int)sizeof(unsigned long long));
        cudaFuncSetAttribute(k_knn, cudaFuncAttributeMaxDynamicSharedMemorySize,
                             WINCAP * (int)sizeof(float4));
        smem_set = 1;
    }

    k_prep<<<N_NODES / 8, 512>>>(x, w_h, b_h, w_s);
    k_sort<<<1, SORT_T, N_NODES * sizeof(unsigned long long)>>>();
    k_knn<<<N_NODES / QPB, QPB, WINCAP * sizeof(float4)>>>();
    k_agglin<<<N_NODES / 8, 512>>>(x, w_lin, b_lin);
    k_stats_part<<<SBLK, 256>>>(0);
    k_stats_fin<<<1, C_DIM>>>(0);
    k_mlp<<<N_NODES / 8, 512>>>(w_p1, b_p1, w_p2, b_p2, gamma2, beta2);
    k_stats_part<<<SBLK, 256>>>(1);
    k_stats_fin<<<1, C_DIM>>>(1);
    k_bn3<<<(N_NODES * C_DIM) / 4 / 256, 256>>>(out, gamma3, beta3);
}

// round 14
// speedup vs baseline: 2.9259x; 2.9190x over previous
#include <cuda_runtime.h>
#include <math.h>

#define N_NODES 16384
#define C_DIM   64
#define KNN     40
#define BUF     21
#define QPB     128       // queries per CTA (kNN)
#define W_HALF  2048      // half rank-window
#define WINCAP  4352      // padded window capacity (>= 2*W_HALF + QPB)
#define SORT_T  1024
#define SBLK    32
#define BN_EPS  1e-5f
#define FBIG    1e30f

// ---------------- scratch (static device globals; no allocation) ----------------
__device__ float4 g_s4[N_NODES];               // coords by original id (w unused)
__device__ float4 g_ss[N_NODES];               // sorted coords (x,y,z,|p|^2)
__device__ int    g_sid[N_NODES];              // sorted pos -> original id
__device__ float  g_h[N_NODES * C_DIM];
__device__ int    g_idx[KNN * N_NODES];
__device__ float  g_ew[KNN * N_NODES];
__device__ float  g_t[N_NODES * C_DIM];
__device__ float  g_wres[N_NODES * C_DIM];
__device__ float  g_ps[2][SBLK][C_DIM], g_pq[2][SBLK][C_DIM];
__device__ float  g_mu2[C_DIM], g_rs2[C_DIM], g_mu3[C_DIM], g_rs3[C_DIM];

// ---------------- K1: h = x@w_h + b_h ; s = x@w_s ----------------
__global__ __launch_bounds__(512) void k_prep(const float* __restrict__ x,
                                              const float* __restrict__ w_h,
                                              const float* __restrict__ b_h,
                                              const float* __restrict__ w_s) {
    __shared__ float whs[C_DIM * C_DIM];
    __shared__ float wss[C_DIM * 4];
    __shared__ float sx[8][C_DIM];
    int tid = threadIdx.x;
    for (int i = tid; i < C_DIM * C_DIM; i += 512) whs[i] = w_h[i];
    if (tid < C_DIM * 3) wss[(tid / 3) * 4 + (tid % 3)] = w_s[tid];
    int g = tid >> 6, c = tid & 63;
    int n = blockIdx.x * 8 + g;
    sx[g][c] = x[n * C_DIM + c];
    __syncthreads();
    float acc = b_h[c];
#pragma unroll
    for (int k2 = 0; k2 < C_DIM; k2++) acc = fmaf(sx[g][k2], whs[k2 * C_DIM + c], acc);
    g_h[n * C_DIM + c] = acc;
    if (c < 4) {
        float sv = 0.f;
        if (c < 3) {
#pragma unroll
            for (int k2 = 0; k2 < C_DIM; k2++) sv = fmaf(sx[g][k2], wss[k2 * 4 + c], sv);
        }
        ((float*)g_s4)[n * 4 + c] = sv;
    }
}

// ---------------- K2: deterministic single-CTA bitonic sort by s.x ----------------
__global__ __launch_bounds__(SORT_T, 1) void k_sort() {
    extern __shared__ unsigned long long sk[];
    int tid = threadIdx.x;
    for (int i = tid; i < N_NODES; i += SORT_T) {
        unsigned int u = __float_as_uint(g_s4[i].x);
        u = (u & 0x80000000u) ? ~u : (u | 0x80000000u);   // sortable uint
        sk[i] = ((unsigned long long)u << 32) | (unsigned int)i;
    }
    __syncthreads();
    for (int k = 2; k <= N_NODES; k <<= 1) {
        for (int j = k >> 1; j >= 1; j >>= 1) {
#pragma unroll
            for (int s = 0; s < N_NODES / 2 / SORT_T; s++) {
                int p = tid + s * SORT_T;
                int i = ((p & ~(j - 1)) << 1) | (p & (j - 1));
                int l = i | j;
                unsigned long long A = sk[i], B = sk[l];
                bool up = ((i & k) == 0);
                if ((A > B) == up) { sk[i] = B; sk[l] = A; }
            }
            __syncthreads();
        }
    }
    for (int i = tid; i < N_NODES; i += SORT_T) {
        unsigned long long kv = sk[i];
        int id = (int)(kv & 0xFFFFFFFFull);
        float4 s = g_s4[id];
        float rp = fmaf(s.x, s.x, fmaf(s.y, s.y, s.z * s.z));
        g_ss[i] = make_float4(s.x, s.y, s.z, rp);
        g_sid[i] = id;
    }
}

// ---------------- K3: windowed exact kNN ----------------
__device__ __forceinline__ void insert40(float (&bd)[KNN], int (&bi)[KNN],
                                         float cd, int ci, bool want) {
    bool placed = !want;
#pragma unroll
    for (int j = KNN - 1; j >= 1; j--) {
        if (!placed) {
            bool sw = cd < bd[j - 1];
            float pu = bd[j - 1];
            int   iu = bi[j - 1];
            bd[j] = sw ? pu : cd;
            bi[j] = sw ? iu : ci;
            placed = !sw;
        }
        if ((j & 7) == 0) {
            if (__all_sync(0xffffffffu, placed)) return;
        }
    }
    if (!placed) { bd[0] = cd; bi[0] = ci; }
}

__device__ __forceinline__ void insert40_ser(float (&bd)[KNN], int (&bi)[KNN],
                                             float cd, int ci) {
    bool placed = false;
#pragma unroll
    for (int j = KNN - 1; j >= 1; j--) {
        if (!placed) {
            bool sw = cd < bd[j - 1];
            float pu = bd[j - 1];
            int   iu = bi[j - 1];
            bd[j] = sw ? pu : cd;
            bi[j] = sw ? iu : ci;
            placed = !sw;
        }
    }
    if (!placed) { bd[0] = cd; bi[0] = ci; }
}

__device__ __forceinline__ void flush_buf(float (&bd)[KNN], int (&bi)[KNN],
                                          float (*bufD)[BUF], int (*bufI)[BUF],
                                          int tid, int& cnt) {
    int mx = cnt;
#pragma unroll
    for (int o = 16; o > 0; o >>= 1)
        mx = max(mx, __shfl_xor_sync(0xffffffffu, mx, o));
    for (int e = 0; e < mx; e++) {
        bool act = e < cnt;
        float d = act ? bufD[tid][e] : FBIG;
        int idv = act ? bufI[tid][e] : 0;
        insert40(bd, bi, d, idv, act && (d < bd[KNN - 1]));
    }
    cnt = 0;
}

__global__ __launch_bounds__(QPB) void k_knn() {
    extern __shared__ float4 win[];        // WINCAP * 16B = 68KB dynamic
    __shared__ float  bufD[QPB][BUF];      // 10.5KB
    __shared__ int    bufI[QPB][BUF];      // 10.5KB
    int tid = threadIdx.x;
    int lane = tid & 31;
    int p = blockIdx.x * QPB + tid;        // my query's sorted position
    float4 qs = g_ss[p];
    float qx2 = -2.f * qs.x, qy2 = -2.f * qs.y, qz2 = -2.f * qs.z;
    float sq = qs.w;
    float bd[KNN]; int bi[KNN];
#pragma unroll
    for (int j = 0; j < KNN; j++) { bd[j] = FBIG; bi[j] = 0; }
    int lo = blockIdx.x * QPB - W_HALF; if (lo < 0) lo = 0;
    int hi = blockIdx.x * QPB + QPB + W_HALF; if (hi > N_NODES) hi = N_NODES;
    int len = hi - lo;
    int cnt = 0;

    // load entire window; pad with +inf rows (t evaluates to +inf -> never inserts)
    const float INF = __int_as_float(0x7f800000);
    for (int i = tid; i < WINCAP; i += QPB)
        win[i] = (i < len) ? g_ss[lo + i] : make_float4(0.f, 0.f, 0.f, INF);
    __syncthreads();

    // main sweep: 12-bit bit-reversed order over [0,4096) decorrelates distance
    // from scan position. Warp-uniform idx -> smem broadcast.
    for (int j = 0; j < 4096; j += 8) {
#pragma unroll
        for (int u = 0; u < 8; u++) {
            int idx = (int)(__brev((unsigned)(j + u)) >> 20);
            float4 c = win[idx];
            float t = fmaf(qx2, c.x, fmaf(qy2, c.y, fmaf(qz2, c.z, c.w)));
            if (t < bd[KNN - 1]) {
                bufD[tid][cnt] = t;
                bufI[tid][cnt] = lo + idx;
                cnt++;
            }
        }
        if (__any_sync(0xffffffffu, cnt >= BUF - 8))
            flush_buf(bd, bi, bufD, bufI, tid, cnt);
    }
    // tail [4096, WINCAP): linear (at most 256 real entries)
    for (int j = 4096; j < WINCAP; j += 8) {
#pragma unroll
        for (int u = 0; u < 8; u++) {
            float4 c = win[j + u];
            float t = fmaf(qx2, c.x, fmaf(qy2, c.y, fmaf(qz2, c.z, c.w)));
            if (t < bd[KNN - 1]) {
                bufD[tid][cnt] = t;
                bufI[tid][cnt] = lo + j + u;
                cnt++;
            }
        }
        if (__any_sync(0xffffffffu, cnt >= BUF - 8))
            flush_buf(bd, bi, bufD, bufI, tid, cnt);
    }
    flush_buf(bd, bi, bufD, bufI, tid, cnt);

    // ---- Phase B: WARP-COOPERATIVE exact extension past the window ----
    // The per-lane serial walk was the rounds-5..13 ~2.2ms pathology: a query
    // ordinary in x but outlying in (y,z) has huge d2_40, so its lane walked
    // O(N) dependent loads, serializing its warp. Now the whole warp processes
    // each needy query: 32 coalesced candidates/step; stop when lane 0 (the
    // x-closest remaining element, by sort monotonicity) prunes.
    float thrd = sq + bd[KNN - 1];          // absolute d^2 of current 40th
    // LEFT (idx < lo; x decreases, dx=qx-x grows as idx decreases)
    {
        bool need = false;
        if (lo > 0) {
            float dxe = qs.x - g_ss[lo - 1].x;
            need = (dxe * dxe < thrd);
        }
        unsigned active = __ballot_sync(0xffffffffu, need);
        while (active) {
            int q = __ffs(active) - 1;
            active &= ~(1u << q);
            float qx = __shfl_sync(0xffffffffu, qs.x, q);
            float qy = __shfl_sync(0xffffffffu, qs.y, q);
            float qz = __shfl_sync(0xffffffffu, qs.z, q);
            float qsq = __shfl_sync(0xffffffffu, sq, q);
            float b39 = __shfl_sync(0xffffffffu, bd[KNN - 1], q);
            float th = qsq + b39;
            int pos = lo - 1;
            bool done = false;
            while (!done) {
                int idx = pos - lane;
                bool val = (idx >= 0);
                float4 c = val ? g_ss[idx] : make_float4(-3e18f, 0.f, 0.f, FBIG);
                float dx = qx - c.x;
                bool prune = !val || (dx * dx >= th);
                float t = fmaf(-2.f * qx, c.x, fmaf(-2.f * qy, c.y, fmaf(-2.f * qz, c.z, c.w)));
                unsigned qual = __ballot_sync(0xffffffffu, !prune && (t < b39));
                while (qual) {
                    int src = __ffs(qual) - 1;
                    qual &= ~(1u << src);
                    float tc = __shfl_sync(0xffffffffu, t, src);
                    int ic = __shfl_sync(0xffffffffu, idx, src);
                    if (lane == q && tc < bd[KNN - 1]) insert40_ser(bd, bi, tc, ic);
                    b39 = __shfl_sync(0xffffffffu, bd[KNN - 1], q);
                }
                th = qsq + b39;
                unsigned pr = __ballot_sync(0xffffffffu, prune);
                if (pr & 1u) done = true;      // lane 0 is x-closest -> monotone stop
                pos -= 32;
            }
            if (lane == q) thrd = qsq + bd[KNN - 1];
        }
    }
    // RIGHT (idx >= hi; x increases, dx=x-qx grows as idx increases)
    {
        bool need = false;
        if (hi < N_NODES) {
            float dxe = g_ss[hi].x - qs.x;
            need = (dxe * dxe < thrd);
        }
        unsigned active = __ballot_sync(0xffffffffu, need);
        while (active) {
            int q = __ffs(active) - 1;
            active &= ~(1u << q);
            float qx = __shfl_sync(0xffffffffu, qs.x, q);
            float qy = __shfl_sync(0xffffffffu, qs.y, q);
            float qz = __shfl_sync(0xffffffffu, qs.z, q);
            float qsq = __shfl_sync(0xffffffffu, sq, q);
            float b39 = __shfl_sync(0xffffffffu, bd[KNN - 1], q);
            float th = qsq + b39;
            int pos = hi;
            bool done = false;
            while (!done) {
                int idx = pos + lane;
                bool val = (idx < N_NODES);
                float4 c = val ? g_ss[idx] : make_float4(3e18f, 0.f, 0.f, FBIG);
                float dx = c.x - qx;
                bool prune = !val || (dx * dx >= th);
                float t = fmaf(-2.f * qx, c.x, fmaf(-2.f * qy, c.y, fmaf(-2.f * qz, c.z, c.w)));
                unsigned qual = __ballot_sync(0xffffffffu, !prune && (t < b39));
                while (qual) {
                    int src = __ffs(qual) - 1;
                    qual &= ~(1u << src);
                    float tc = __shfl_sync(0xffffffffu, t, src);
                    int ic = __shfl_sync(0xffffffffu, idx, src);
                    if (lane == q && tc < bd[KNN - 1]) insert40_ser(bd, bi, tc, ic);
                    b39 = __shfl_sync(0xffffffffu, bd[KNN - 1], q);
                }
                th = qsq + b39;
                unsigned pr = __ballot_sync(0xffffffffu, prune);
                if (pr & 1u) done = true;
                pos += 32;
            }
            if (lane == q) thrd = qsq + bd[KNN - 1];
        }
    }

    int qid = g_sid[p];
#pragma unroll
    for (int j = 0; j < KNN; j++) {
        g_idx[j * N_NODES + qid] = g_sid[bi[j]];
        g_ew[j * N_NODES + qid] = expf(-(sq + bd[j] + 1e-6f));
    }
}

// ---------------- K4: gather-aggregate (mean,max) + lin(cat) + residual ----------------
__global__ __launch_bounds__(512) void k_agglin(const float* __restrict__ x,
                                                const float* __restrict__ w_lin,
                                                const float* __restrict__ b_lin) {
    __shared__ float Ws[128 * 64];
    __shared__ float scat[8][128];
    __shared__ float sx[8][64];
    int tid = threadIdx.x;
    for (int i = tid; i < (128 * 64) / 4; i += 512)
        ((float4*)Ws)[i] = ((const float4*)w_lin)[i];
    int g = tid >> 6, c = tid & 63;
    int n = blockIdx.x * 8 + g;
    float mean = 0.f, mx = -FBIG;
#pragma unroll 1
    for (int k2 = 0; k2 < KNN; k2 += 8) {
        int ii[8]; float ww[8];
#pragma unroll
        for (int u = 0; u < 8; u++) {
            ii[u] = g_idx[(k2 + u) * N_NODES + n];
            ww[u] = g_ew[(k2 + u) * N_NODES + n];
        }
#pragma unroll
        for (int u = 0; u < 8; u++) {
            float m = ww[u] * g_h[ii[u] * C_DIM + c];
            mean += m;
            mx = fmaxf(mx, m);
        }
    }
    mean *= (1.0f / KNN);
    float xv = x[n * C_DIM + c];
    scat[g][c] = mean;
    scat[g][64 + c] = mx;
    sx[g][c] = xv;
    __syncthreads();
    float acc = b_lin[c];
#pragma unroll
    for (int j = 0; j < 128; j++) acc = fmaf(scat[g][j], Ws[j * 64 + c], acc);
#pragma unroll
    for (int j = 0; j < 64; j++)
        acc = fmaf(sx[g][j], __ldg(&w_lin[(128 + j) * 64 + c]), acc);
    g_t[n * C_DIM + c] = acc + xv;
}

// ---------------- coalesced deterministic BN stats ----------------
__global__ __launch_bounds__(256) void k_stats_part(int which) {
    const float* v = (which == 0) ? g_t : g_wres;
    __shared__ float4 rs_[256], rq_[256];
    int tid = threadIdx.x;
    int cg = tid & 15, ns = tid >> 4;
    float4 s = {0.f, 0.f, 0.f, 0.f}, sq = {0.f, 0.f, 0.f, 0.f};
    int nbase = blockIdx.x * (N_NODES / SBLK);
#pragma unroll 4
    for (int n = nbase + ns; n < nbase + (N_NODES / SBLK); n += 16) {
        float4 val = ((const float4*)v)[n * 16 + cg];
        s.x += val.x; s.y += val.y; s.z += val.z; s.w += val.w;
        sq.x = fmaf(val.x, val.x, sq.x); sq.y = fmaf(val.y, val.y, sq.y);
        sq.z = fmaf(val.z, val.z, sq.z); sq.w = fmaf(val.w, val.w, sq.w);
    }
    rs_[tid] = s; rq_[tid] = sq;
    __syncthreads();
    for (int off = 128; off >= 16; off >>= 1) {
        if (tid < off) {
            float4 a = rs_[tid], b = rs_[tid + off];
            a.x += b.x; a.y += b.y; a.z += b.z; a.w += b.w;
            rs_[tid] = a;
            float4 c = rq_[tid], d = rq_[tid + off];
            c.x += d.x; c.y += d.y; c.z += d.z; c.w += d.w;
            rq_[tid] = c;
        }
        __syncthreads();
    }
    if (tid < 16) {
        float4 a = rs_[tid], b = rq_[tid];
        g_ps[which][blockIdx.x][tid * 4 + 0] = a.x;
        g_ps[which][blockIdx.x][tid * 4 + 1] = a.y;
        g_ps[which][blockIdx.x][tid * 4 + 2] = a.z;
        g_ps[which][blockIdx.x][tid * 4 + 3] = a.w;
        g_pq[which][blockIdx.x][tid * 4 + 0] = b.x;
        g_pq[which][blockIdx.x][tid * 4 + 1] = b.y;
        g_pq[which][blockIdx.x][tid * 4 + 2] = b.z;
        g_pq[which][blockIdx.x][tid * 4 + 3] = b.w;
    }
}

__global__ void k_stats_fin(int which) {
    int c = threadIdx.x;
    float s = 0.f, s2 = 0.f;
#pragma unroll
    for (int b = 0; b < SBLK; b++) {
        s += g_ps[which][b][c];
        s2 += g_pq[which][b][c];
    }
    float m = s * (1.0f / N_NODES);
    float var = s2 * (1.0f / N_NODES) - m * m;
    if (which == 0) { g_mu2[c] = m; g_rs2[c] = rsqrtf(var + BN_EPS); }
    else            { g_mu3[c] = m; g_rs3[c] = rsqrtf(var + BN_EPS); }
}

// ---------------- K5: BN2 + MLP + residual ----------------
__global__ __launch_bounds__(512) void k_mlp(const float* __restrict__ w_p1,
                                             const float* __restrict__ b_p1,
                                             const float* __restrict__ w_p2,
                                             const float* __restrict__ b_p2,
                                             const float* __restrict__ gamma2,
                                             const float* __restrict__ beta2) {
    __shared__ float w1s[64 * 64], w2s[64 * 64];
    __shared__ float sy[8][64], sa[8][64];
    int tid = threadIdx.x;
    for (int i = tid; i < (64 * 64) / 4; i += 512) {
        ((float4*)w1s)[i] = ((const float4*)w_p1)[i];
        ((float4*)w2s)[i] = ((const float4*)w_p2)[i];
    }
    int g = tid >> 6, c = tid & 63;
    int n = blockIdx.x * 8 + g;
    float y = gamma2[c] * (g_t[n * 64 + c] - g_mu2[c]) * g_rs2[c] + beta2[c];
    sy[g][c] = y;
    __syncthreads();
    float a = b_p1[c];
#pragma unroll
    for (int k2 = 0; k2 < 64; k2++) a = fmaf(sy[g][k2], w1s[k2 * 64 + c], a);
    a = (a > 0.f) ? a : expm1f(a);
    sa[g][c] = a;
    __syncthreads();
    float z = b_p2[c];
#pragma unroll
    for (int k2 = 0; k2 < 64; k2++) z = fmaf(sa[g][k2], w2s[k2 * 64 + c], z);
    g_wres[n * 64 + c] = y + z;
}

// ---------------- K6: out = BN3(wres) ----------------
__global__ void k_bn3(float* __restrict__ out,
                      const float* __restrict__ gamma3,
                      const float* __restrict__ beta3) {
    int i = blockIdx.x * 256 + threadIdx.x;
    float4 wv = ((const float4*)g_wres)[i];
    int cb = (i & 15) * 4;
    float4 o;
    o.x = gamma3[cb + 0] * (wv.x - g_mu3[cb + 0]) * g_rs3[cb + 0] + beta3[cb + 0];
    o.y = gamma3[cb + 1] * (wv.y - g_mu3[cb + 1]) * g_rs3[cb + 1] + beta3[cb + 1];
    o.z = gamma3[cb + 2] * (wv.z - g_mu3[cb + 2]) * g_rs3[cb + 2] + beta3[cb + 2];
    o.w = gamma3[cb + 3] * (wv.w - g_mu3[cb + 3]) * g_rs3[cb + 3] + beta3[cb + 3];
    ((float4*)out)[i] = o;
}

// ---------------- launch ----------------
extern "C" void kernel_launch(void* const* d_in, const int* in_sizes, int n_in,
                              void* d_out, int out_size) {
    const float* x      = (const float*)d_in[0];
    const float* w_s    = (const float*)d_in[1];
    const float* w_h    = (const float*)d_in[2];
    const float* b_h    = (const float*)d_in[3];
    const float* w_lin  = (const float*)d_in[4];
    const float* b_lin  = (const float*)d_in[5];
    const float* w_p1   = (const float*)d_in[6];
    const float* b_p1   = (const float*)d_in[7];
    const float* w_p2   = (const float*)d_in[8];
    const float* b_p2   = (const float*)d_in[9];
    const float* gamma2 = (const float*)d_in[10];
    const float* beta2  = (const float*)d_in[11];
    const float* gamma3 = (const float*)d_in[12];
    const float* beta3  = (const float*)d_in[13];
    float* out = (float*)d_out;

    static int smem_set = 0;
    if (!smem_set) {
        cudaFuncSetAttribute(k_sort, cudaFuncAttributeMaxDynamicSharedMemorySize,
                             N_NODES * (int)sizeof(unsigned long long));
        cudaFuncSetAttribute(k_knn, cudaFuncAttributeMaxDynamicSharedMemorySize,
                             WINCAP * (int)sizeof(float4));
        smem_set = 1;
    }

    k_prep<<<N_NODES / 8, 512>>>(x, w_h, b_h, w_s);
    k_sort<<<1, SORT_T, N_NODES * sizeof(unsigned long long)>>>();
    k_knn<<<N_NODES / QPB, QPB, WINCAP * sizeof(float4)>>>();
    k_agglin<<<N_NODES / 8, 512>>>(x, w_lin, b_lin);
    k_stats_part<<<SBLK, 256>>>(0);
    k_stats_fin<<<1, C_DIM>>>(0);
    k_mlp<<<N_NODES / 8, 512>>>(w_p1, b_p1, w_p2, b_p2, gamma2, beta2);
    k_stats_part<<<SBLK, 256>>>(1);
    k_stats_fin<<<1, C_DIM>>>(1);
    k_bn3<<<(N_NODES * C_DIM) / 4 / 256, 256>>>(out, gamma3, beta3);
}

// round 15
// speedup vs baseline: 3.2983x; 1.1273x over previous
#include <cuda_runtime.h>
#include <math.h>

#define N_NODES 16384
#define C_DIM   64
#define KNN     40
#define BUF     21
#define QPB     128       // queries per CTA (kNN)
#define W_HALF  2048      // half rank-window
#define WINCAP  4352      // padded window capacity (>= 2*W_HALF + QPB)
#define SBLK    32
#define BN_EPS  1e-5f
#define FBIG    1e30f

// ---------------- scratch (static device globals; no allocation) ----------------
__device__ float4 g_s4[N_NODES];               // coords by original id (w unused)
__device__ float4 g_ss[N_NODES];               // sorted coords (x,y,z,|p|^2)
__device__ int    g_sid[N_NODES];              // sorted pos -> original id
__device__ unsigned long long g_keys[N_NODES]; // sort keys (x-sortable | id)
__device__ float  g_h[N_NODES * C_DIM];
__device__ int    g_idx[KNN * N_NODES];
__device__ float  g_ew[KNN * N_NODES];
__device__ float  g_t[N_NODES * C_DIM];
__device__ float  g_wres[N_NODES * C_DIM];
__device__ float  g_ps[2][SBLK][C_DIM], g_pq[2][SBLK][C_DIM];
__device__ float  g_mu2[C_DIM], g_rs2[C_DIM], g_mu3[C_DIM], g_rs3[C_DIM];

// ---------------- K1: h = x@w_h + b_h ; s = x@w_s ----------------
__global__ __launch_bounds__(512) void k_prep(const float* __restrict__ x,
                                              const float* __restrict__ w_h,
                                              const float* __restrict__ b_h,
                                              const float* __restrict__ w_s) {
    __shared__ float whs[C_DIM * C_DIM];
    __shared__ float wss[C_DIM * 4];
    __shared__ float sx[8][C_DIM];
    int tid = threadIdx.x;
    for (int i = tid; i < C_DIM * C_DIM; i += 512) whs[i] = w_h[i];
    if (tid < C_DIM * 3) wss[(tid / 3) * 4 + (tid % 3)] = w_s[tid];
    int g = tid >> 6, c = tid & 63;
    int n = blockIdx.x * 8 + g;
    sx[g][c] = x[n * C_DIM + c];
    __syncthreads();
    float acc = b_h[c];
#pragma unroll
    for (int k2 = 0; k2 < C_DIM; k2++) acc = fmaf(sx[g][k2], whs[k2 * C_DIM + c], acc);
    g_h[n * C_DIM + c] = acc;
    if (c < 4) {
        float sv = 0.f;
        if (c < 3) {
#pragma unroll
            for (int k2 = 0; k2 < C_DIM; k2++) sv = fmaf(sx[g][k2], wss[k2 * 4 + c], sv);
        }
        ((float*)g_s4)[n * 4 + c] = sv;
    }
}

// ---------------- K2: multi-CTA bitonic sort by s.x (identical network to the
// single-CTA version -> bit-identical output, but 8 CTAs in parallel + tiny
// global phases instead of 105 barrier-phases on one SM) ----------------

// 2a: per-chunk bitonic (k = 2..2048) in smem; 8 CTAs x 2048 elements
__global__ __launch_bounds__(1024) void k_sort_a() {
    __shared__ unsigned long long sk[2048];
    int tid = threadIdx.x;
    int base = blockIdx.x * 2048;
#pragma unroll
    for (int s = 0; s < 2; s++) {
        int li = tid + s * 1024;
        unsigned u = __float_as_uint(g_s4[base + li].x);
        u = (u & 0x80000000u) ? ~u : (u | 0x80000000u);   // sortable uint
        sk[li] = ((unsigned long long)u << 32) | (unsigned)(base + li);
    }
    __syncthreads();
    for (int k = 2; k <= 2048; k <<= 1) {
        for (int j = k >> 1; j >= 1; j >>= 1) {
            int li = ((tid & ~(j - 1)) << 1) | (tid & (j - 1));
            int ll = li | j;
            bool up = (((base + li) & k) == 0);
            unsigned long long A = sk[li], B = sk[ll];
            if ((A > B) == up) { sk[li] = B; sk[ll] = A; }
            __syncthreads();
        }
    }
#pragma unroll
    for (int s = 0; s < 2; s++) {
        int li = tid + s * 1024;
        g_keys[base + li] = sk[li];
    }
}

// 2b: one global pair-swap phase (j >= 2048); 8 CTAs x 1024 pairs
__global__ __launch_bounds__(1024) void k_sort_g(int k, int j) {
    int p = blockIdx.x * 1024 + threadIdx.x;
    int i = ((p & ~(j - 1)) << 1) | (p & (j - 1));
    int l = i | j;
    bool up = ((i & k) == 0);
    unsigned long long A = g_keys[i], B = g_keys[l];
    if ((A > B) == up) { g_keys[i] = B; g_keys[l] = A; }
}

// 2c: finish merge step k: all j <= 1024 phases within each 2048-chunk in smem.
// fin=1 (last step) additionally writes g_ss / g_sid.
__global__ __launch_bounds__(1024) void k_sort_b(int k, int fin) {
    __shared__ unsigned long long sk[2048];
    int tid = threadIdx.x;
    int base = blockIdx.x * 2048;
    sk[tid] = g_keys[base + tid];
    sk[tid + 1024] = g_keys[base + tid + 1024];
    __syncthreads();
    for (int j = 1024; j >= 1; j >>= 1) {
        int li = ((tid & ~(j - 1)) << 1) | (tid & (j - 1));
        int ll = li | j;
        bool up = (((base + li) & k) == 0);
        unsigned long long A = sk[li], B = sk[ll];
        if ((A > B) == up) { sk[li] = B; sk[ll] = A; }
        __syncthreads();
    }
    if (!fin) {
        g_keys[base + tid] = sk[tid];
        g_keys[base + tid + 1024] = sk[tid + 1024];
    } else {
#pragma unroll
        for (int s = 0; s < 2; s++) {
            int li = tid + s * 1024;
            unsigned long long kv = sk[li];
            int id = (int)(kv & 0xFFFFFFFFull);
            float4 sv = g_s4[id];
            float rp = fmaf(sv.x, sv.x, fmaf(sv.y, sv.y, sv.z * sv.z));
            g_ss[base + li] = make_float4(sv.x, sv.y, sv.z, rp);
            g_sid[base + li] = id;
        }
    }
}

// ---------------- K3: windowed exact kNN ----------------
__device__ __forceinline__ void insert40(float (&bd)[KNN], int (&bi)[KNN],
                                         float cd, int ci, bool want) {
    bool placed = !want;
#pragma unroll
    for (int j = KNN - 1; j >= 1; j--) {
        if (!placed) {
            bool sw = cd < bd[j - 1];
            float pu = bd[j - 1];
            int   iu = bi[j - 1];
            bd[j] = sw ? pu : cd;
            bi[j] = sw ? iu : ci;
            placed = !sw;
        }
        if ((j & 7) == 0) {
            if (__all_sync(0xffffffffu, placed)) return;
        }
    }
    if (!placed) { bd[0] = cd; bi[0] = ci; }
}

__device__ __forceinline__ void insert40_ser(float (&bd)[KNN], int (&bi)[KNN],
                                             float cd, int ci) {
    bool placed = false;
#pragma unroll
    for (int j = KNN - 1; j >= 1; j--) {
        if (!placed) {
            bool sw = cd < bd[j - 1];
            float pu = bd[j - 1];
            int   iu = bi[j - 1];
            bd[j] = sw ? pu : cd;
            bi[j] = sw ? iu : ci;
            placed = !sw;
        }
    }
    if (!placed) { bd[0] = cd; bi[0] = ci; }
}

__device__ __forceinline__ void flush_buf(float (&bd)[KNN], int (&bi)[KNN],
                                          float (*bufD)[BUF], int (*bufI)[BUF],
                                          int tid, int& cnt) {
    int mx = cnt;
#pragma unroll
    for (int o = 16; o > 0; o >>= 1)
        mx = max(mx, __shfl_xor_sync(0xffffffffu, mx, o));
    for (int e = 0; e < mx; e++) {
        bool act = e < cnt;
        float d = act ? bufD[tid][e] : FBIG;
        int idv = act ? bufI[tid][e] : 0;
        insert40(bd, bi, d, idv, act && (d < bd[KNN - 1]));
    }
    cnt = 0;
}

__global__ __launch_bounds__(QPB) void k_knn() {
    extern __shared__ float4 win[];        // WINCAP * 16B = 68KB dynamic
    __shared__ float  bufD[QPB][BUF];      // 10.5KB
    __shared__ int    bufI[QPB][BUF];      // 10.5KB
    int tid = threadIdx.x;
    int lane = tid & 31;
    int p = blockIdx.x * QPB + tid;        // my query's sorted position
    float4 qs = g_ss[p];
    float qx2 = -2.f * qs.x, qy2 = -2.f * qs.y, qz2 = -2.f * qs.z;
    float sq = qs.w;
    float bd[KNN]; int bi[KNN];
#pragma unroll
    for (int j = 0; j < KNN; j++) { bd[j] = FBIG; bi[j] = 0; }
    int lo = blockIdx.x * QPB - W_HALF; if (lo < 0) lo = 0;
    int hi = blockIdx.x * QPB + QPB + W_HALF; if (hi > N_NODES) hi = N_NODES;
    int len = hi - lo;
    int cnt = 0;

    // load entire window; pad with +inf rows (t evaluates to +inf -> never inserts)
    const float INF = __int_as_float(0x7f800000);
    for (int i = tid; i < WINCAP; i += QPB)
        win[i] = (i < len) ? g_ss[lo + i] : make_float4(0.f, 0.f, 0.f, INF);
    __syncthreads();

    // main sweep: 12-bit bit-reversed order over [0,4096) decorrelates distance
    // from scan position. Warp-uniform idx -> smem broadcast.
    for (int j = 0; j < 4096; j += 8) {
#pragma unroll
        for (int u = 0; u < 8; u++) {
            int idx = (int)(__brev((unsigned)(j + u)) >> 20);
            float4 c = win[idx];
            float t = fmaf(qx2, c.x, fmaf(qy2, c.y, fmaf(qz2, c.z, c.w)));
            if (t < bd[KNN - 1]) {
                bufD[tid][cnt] = t;
                bufI[tid][cnt] = lo + idx;
                cnt++;
            }
        }
        if (__any_sync(0xffffffffu, cnt >= BUF - 8))
            flush_buf(bd, bi, bufD, bufI, tid, cnt);
    }
    // tail [4096, WINCAP): linear (at most 256 real entries)
    for (int j = 4096; j < WINCAP; j += 8) {
#pragma unroll
        for (int u = 0; u < 8; u++) {
            float4 c = win[j + u];
            float t = fmaf(qx2, c.x, fmaf(qy2, c.y, fmaf(qz2, c.z, c.w)));
            if (t < bd[KNN - 1]) {
                bufD[tid][cnt] = t;
                bufI[tid][cnt] = lo + j + u;
                cnt++;
            }
        }
        if (__any_sync(0xffffffffu, cnt >= BUF - 8))
            flush_buf(bd, bi, bufD, bufI, tid, cnt);
    }
    flush_buf(bd, bi, bufD, bufI, tid, cnt);

    // ---- Phase B: WARP-COOPERATIVE exact extension past the window ----
    float thrd = sq + bd[KNN - 1];          // absolute d^2 of current 40th
    // LEFT (idx < lo; x decreases, dx=qx-x grows as idx decreases)
    {
        bool need = false;
        if (lo > 0) {
            float dxe = qs.x - g_ss[lo - 1].x;
            need = (dxe * dxe < thrd);
        }
        unsigned active = __ballot_sync(0xffffffffu, need);
        while (active) {
            int q = __ffs(active) - 1;
            active &= ~(1u << q);
            float qx = __shfl_sync(0xffffffffu, qs.x, q);
            float qy = __shfl_sync(0xffffffffu, qs.y, q);
            float qz = __shfl_sync(0xffffffffu, qs.z, q);
            float qsq = __shfl_sync(0xffffffffu, sq, q);
            float b39 = __shfl_sync(0xffffffffu, bd[KNN - 1], q);
            float th = qsq + b39;
            int pos = lo - 1;
            bool done = false;
            while (!done) {
                int idx = pos - lane;
                bool val = (idx >= 0);
                float4 c = val ? g_ss[idx] : make_float4(-3e18f, 0.f, 0.f, FBIG);
                float dx = qx - c.x;
                bool prune = !val || (dx * dx >= th);
                float t = fmaf(-2.f * qx, c.x, fmaf(-2.f * qy, c.y, fmaf(-2.f * qz, c.z, c.w)));
                unsigned qual = __ballot_sync(0xffffffffu, !prune && (t < b39));
                while (qual) {
                    int src = __ffs(qual) - 1;
                    qual &= ~(1u << src);
                    float tc = __shfl_sync(0xffffffffu, t, src);
                    int ic = __shfl_sync(0xffffffffu, idx, src);
                    if (lane == q && tc < bd[KNN - 1]) insert40_ser(bd, bi, tc, ic);
                    b39 = __shfl_sync(0xffffffffu, bd[KNN - 1], q);
                }
                th = qsq + b39;
                unsigned pr = __ballot_sync(0xffffffffu, prune);
                if (pr & 1u) done = true;      // lane 0 is x-closest -> monotone stop
                pos -= 32;
            }
            if (lane == q) thrd = qsq + bd[KNN - 1];
        }
    }
    // RIGHT (idx >= hi; x increases, dx=x-qx grows as idx increases)
    {
        bool need = false;
        if (hi < N_NODES) {
            float dxe = g_ss[hi].x - qs.x;
            need = (dxe * dxe < thrd);
        }
        unsigned active = __ballot_sync(0xffffffffu, need);
        while (active) {
            int q = __ffs(active) - 1;
            active &= ~(1u << q);
            float qx = __shfl_sync(0xffffffffu, qs.x, q);
            float qy = __shfl_sync(0xffffffffu, qs.y, q);
            float qz = __shfl_sync(0xffffffffu, qs.z, q);
            float qsq = __shfl_sync(0xffffffffu, sq, q);
            float b39 = __shfl_sync(0xffffffffu, bd[KNN - 1], q);
            float th = qsq + b39;
            int pos = hi;
            bool done = false;
            while (!done) {
                int idx = pos + lane;
                bool val = (idx < N_NODES);
                float4 c = val ? g_ss[idx] : make_float4(3e18f, 0.f, 0.f, FBIG);
                float dx = c.x - qx;
                bool prune = !val || (dx * dx >= th);
                float t = fmaf(-2.f * qx, c.x, fmaf(-2.f * qy, c.y, fmaf(-2.f * qz, c.z, c.w)));
                unsigned qual = __ballot_sync(0xffffffffu, !prune && (t < b39));
                while (qual) {
                    int src = __ffs(qual) - 1;
                    qual &= ~(1u << src);
                    float tc = __shfl_sync(0xffffffffu, t, src);
                    int ic = __shfl_sync(0xffffffffu, idx, src);
                    if (lane == q && tc < bd[KNN - 1]) insert40_ser(bd, bi, tc, ic);
                    b39 = __shfl_sync(0xffffffffu, bd[KNN - 1], q);
                }
                th = qsq + b39;
                unsigned pr = __ballot_sync(0xffffffffu, prune);
                if (pr & 1u) done = true;
                pos += 32;
            }
            if (lane == q) thrd = qsq + bd[KNN - 1];
        }
    }

    int qid = g_sid[p];
#pragma unroll
    for (int j = 0; j < KNN; j++) {
        g_idx[j * N_NODES + qid] = g_sid[bi[j]];
        g_ew[j * N_NODES + qid] = expf(-(sq + bd[j] + 1e-6f));
    }
}

// ---------------- K4: gather-aggregate (mean,max) + lin(cat) + residual ----------------
__global__ __launch_bounds__(512) void k_agglin(const float* __restrict__ x,
                                                const float* __restrict__ w_lin,
                                                const float* __restrict__ b_lin) {
    __shared__ float Ws[128 * 64];
    __shared__ float scat[8][128];
    __shared__ float sx[8][64];
    int tid = threadIdx.x;
    for (int i = tid; i < (128 * 64) / 4; i += 512)
        ((float4*)Ws)[i] = ((const float4*)w_lin)[i];
    int g = tid >> 6, c = tid & 63;
    int n = blockIdx.x * 8 + g;
    float mean = 0.f, mx = -FBIG;
#pragma unroll 1
    for (int k2 = 0; k2 < KNN; k2 += 8) {
        int ii[8]; float ww[8];
#pragma unroll
        for (int u = 0; u < 8; u++) {
            ii[u] = g_idx[(k2 + u) * N_NODES + n];
            ww[u] = g_ew[(k2 + u) * N_NODES + n];
        }
#pragma unroll
        for (int u = 0; u < 8; u++) {
            float m = ww[u] * g_h[ii[u] * C_DIM + c];
            mean += m;
            mx = fmaxf(mx, m);
        }
    }
    mean *= (1.0f / KNN);
    float xv = x[n * C_DIM + c];
    scat[g][c] = mean;
    scat[g][64 + c] = mx;
    sx[g][c] = xv;
    __syncthreads();
    float acc = b_lin[c];
#pragma unroll
    for (int j = 0; j < 128; j++) acc = fmaf(scat[g][j], Ws[j * 64 + c], acc);
#pragma unroll
    for (int j = 0; j < 64; j++)
        acc = fmaf(sx[g][j], __ldg(&w_lin[(128 + j) * 64 + c]), acc);
    g_t[n * C_DIM + c] = acc + xv;
}

// ---------------- coalesced deterministic BN stats ----------------
__global__ __launch_bounds__(256) void k_stats_part(int which) {
    const float* v = (which == 0) ? g_t : g_wres;
    __shared__ float4 rs_[256], rq_[256];
    int tid = threadIdx.x;
    int cg = tid & 15, ns = tid >> 4;
    float4 s = {0.f, 0.f, 0.f, 0.f}, sq = {0.f, 0.f, 0.f, 0.f};
    int nbase = blockIdx.x * (N_NODES / SBLK);
#pragma unroll 4
    for (int n = nbase + ns; n < nbase + (N_NODES / SBLK); n += 16) {
        float4 val = ((const float4*)v)[n * 16 + cg];
        s.x += val.x; s.y += val.y; s.z += val.z; s.w += val.w;
        sq.x = fmaf(val.x, val.x, sq.x); sq.y = fmaf(val.y, val.y, sq.y);
        sq.z = fmaf(val.z, val.z, sq.z); sq.w = fmaf(val.w, val.w, sq.w);
    }
    rs_[tid] = s; rq_[tid] = sq;
    __syncthreads();
    for (int off = 128; off >= 16; off >>= 1) {
        if (tid < off) {
            float4 a = rs_[tid], b = rs_[tid + off];
            a.x += b.x; a.y += b.y; a.z += b.z; a.w += b.w;
            rs_[tid] = a;
            float4 c = rq_[tid], d = rq_[tid + off];
            c.x += d.x; c.y += d.y; c.z += d.z; c.w += d.w;
            rq_[tid] = c;
        }
        __syncthreads();
    }
    if (tid < 16) {
        float4 a = rs_[tid], b = rq_[tid];
        g_ps[which][blockIdx.x][tid * 4 + 0] = a.x;
        g_ps[which][blockIdx.x][tid * 4 + 1] = a.y;
        g_ps[which][blockIdx.x][tid * 4 + 2] = a.z;
        g_ps[which][blockIdx.x][tid * 4 + 3] = a.w;
        g_pq[which][blockIdx.x][tid * 4 + 0] = b.x;
        g_pq[which][blockIdx.x][tid * 4 + 1] = b.y;
        g_pq[which][blockIdx.x][tid * 4 + 2] = b.z;
        g_pq[which][blockIdx.x][tid * 4 + 3] = b.w;
    }
}

__global__ void k_stats_fin(int which) {
    int c = threadIdx.x;
    float s = 0.f, s2 = 0.f;
#pragma unroll
    for (int b = 0; b < SBLK; b++) {
        s += g_ps[which][b][c];
        s2 += g_pq[which][b][c];
    }
    float m = s * (1.0f / N_NODES);
    float var = s2 * (1.0f / N_NODES) - m * m;
    if (which == 0) { g_mu2[c] = m; g_rs2[c] = rsqrtf(var + BN_EPS); }
    else            { g_mu3[c] = m; g_rs3[c] = rsqrtf(var + BN_EPS); }
}

// ---------------- K5: BN2 + MLP + residual ----------------
__global__ __launch_bounds__(512) void k_mlp(const float* __restrict__ w_p1,
                                             const float* __restrict__ b_p1,
                                             const float* __restrict__ w_p2,
                                             const float* __restrict__ b_p2,
                                             const float* __restrict__ gamma2,
                                             const float* __restrict__ beta2) {
    __shared__ float w1s[64 * 64], w2s[64 * 64];
    __shared__ float sy[8][64], sa[8][64];
    int tid = threadIdx.x;
    for (int i = tid; i < (64 * 64) / 4; i += 512) {
        ((float4*)w1s)[i] = ((const float4*)w_p1)[i];
        ((float4*)w2s)[i] = ((const float4*)w_p2)[i];
    }
    int g = tid >> 6, c = tid & 63;
    int n = blockIdx.x * 8 + g;
    float y = gamma2[c] * (g_t[n * 64 + c] - g_mu2[c]) * g_rs2[c] + beta2[c];
    sy[g][c] = y;
    __syncthreads();
    float a = b_p1[c];
#pragma unroll
    for (int k2 = 0; k2 < 64; k2++) a = fmaf(sy[g][k2], w1s[k2 * 64 + c], a);
    a = (a > 0.f) ? a : expm1f(a);
    sa[g][c] = a;
    __syncthreads();
    float z = b_p2[c];
#pragma unroll
    for (int k2 = 0; k2 < 64; k2++) z = fmaf(sa[g][k2], w2s[k2 * 64 + c], z);
    g_wres[n * 64 + c] = y + z;
}

// ---------------- K6: out = BN3(wres) ----------------
__global__ void k_bn3(float* __restrict__ out,
                      const float* __restrict__ gamma3,
                      const float* __restrict__ beta3) {
    int i = blockIdx.x * 256 + threadIdx.x;
    float4 wv = ((const float4*)g_wres)[i];
    int cb = (i & 15) * 4;
    float4 o;
    o.x = gamma3[cb + 0] * (wv.x - g_mu3[cb + 0]) * g_rs3[cb + 0] + beta3[cb + 0];
    o.y = gamma3[cb + 1] * (wv.y - g_mu3[cb + 1]) * g_rs3[cb + 1] + beta3[cb + 1];
    o.z = gamma3[cb + 2] * (wv.z - g_mu3[cb + 2]) * g_rs3[cb + 2] + beta3[cb + 2];
    o.w = gamma3[cb + 3] * (wv.w - g_mu3[cb + 3]) * g_rs3[cb + 3] + beta3[cb + 3];
    ((float4*)out)[i] = o;
}

// ---------------- launch ----------------
extern "C" void kernel_launch(void* const* d_in, const int* in_sizes, int n_in,
                              void* d_out, int out_size) {
    const float* x      = (const float*)d_in[0];
    const float* w_s    = (const float*)d_in[1];
    const float* w_h    = (const float*)d_in[2];
    const float* b_h    = (const float*)d_in[3];
    const float* w_lin  = (const float*)d_in[4];
    const float* b_lin  = (const float*)d_in[5];
    const float* w_p1   = (const float*)d_in[6];
    const float* b_p1   = (const float*)d_in[7];
    const float* w_p2   = (const float*)d_in[8];
    const float* b_p2   = (const float*)d_in[9];
    const float* gamma2 = (const float*)d_in[10];
    const float* beta2  = (const float*)d_in[11];
    const float* gamma3 = (const float*)d_in[12];
    const float* beta3  = (const float*)d_in[13];
    float* out = (float*)d_out;

    static int smem_set = 0;
    if (!smem_set) {
        cudaFuncSetAttribute(k_knn, cudaFuncAttributeMaxDynamicSharedMemorySize,
                             WINCAP * (int)sizeof(float4));
        smem_set = 1;
    }

    k_prep<<<N_NODES / 8, 512>>>(x, w_h, b_h, w_s);

    // parallel bitonic sort (identical comparison network to single-CTA version)
    k_sort_a<<<8, 1024>>>();
    for (int k = 4096; k <= N_NODES; k <<= 1) {
        for (int j = k >> 1; j >= 2048; j >>= 1)
            k_sort_g<<<8, 1024>>>(k, j);
        k_sort_b<<<8, 1024>>>(k, (k == N_NODES) ? 1 : 0);
    }

    k_knn<<<N_NODES / QPB, QPB, WINCAP * sizeof(float4)>>>();
    k_agglin<<<N_NODES / 8, 512>>>(x, w_lin, b_lin);
    k_stats_part<<<SBLK, 256>>>(0);
    k_stats_fin<<<1, C_DIM>>>(0);
    k_mlp<<<N_NODES / 8, 512>>>(w_p1, b_p1, w_p2, b_p2, gamma2, beta2);
    k_stats_part<<<SBLK, 256>>>(1);
    k_stats_fin<<<1, C_DIM>>>(1);
    k_bn3<<<(N_NODES * C_DIM) / 4 / 256, 256>>>(out, gamma3, beta3);
}